// round 1
// baseline (speedup 1.0000x reference)
#include <cuda_runtime.h>
#include <cstdint>

// Tuple output layout in d_out (fp32):
//   [0            , U*64)        user_emb1  = all_emb1[:U]
//   [U*64         , N*64)        item_emb1  = all_emb1[U:]
//   [N*64         , (N+U)*64)    user_emb2
//   [(N+U)*64     , (N+U+I)*64)  item_emb2
// So the graph SpMM writes directly into out[0 : N*64).

#define TPB 256
#define D64 64  // embedding dim

// 16 threads cooperate on one edge: each thread owns one float4 (16B) of the
// 256B row. Gather src row, scale by val, vector-red into dst row.

__global__ void spmm_edges(const int* __restrict__ rows,
                           const int* __restrict__ cols,
                           const float* __restrict__ vals,
                           const float* __restrict__ src,
                           float* __restrict__ dst,
                           int n_edges) {
    long long t = (long long)blockIdx.x * TPB + threadIdx.x;
    int e = (int)(t >> 4);
    if (e >= n_edges) return;
    int lane = (int)(t & 15);

    int r = rows[e];
    int c = cols[e];
    float v = vals[e];

    const float4* s = reinterpret_cast<const float4*>(src + (long long)c * D64) + lane;
    float4 x = *s;
    x.x *= v; x.y *= v; x.z *= v; x.w *= v;

    float4* d = reinterpret_cast<float4*>(dst + (long long)r * D64) + lane;
    asm volatile("red.global.add.v4.f32 [%0], {%1,%2,%3,%4};"
                 :: "l"(d), "f"(x.x), "f"(x.y), "f"(x.z), "f"(x.w)
                 : "memory");
}

// Graph SpMM variant: source is logical concat(user_emb, item_emb) without
// materializing it — branch on col index.
__global__ void spmm_edges_concat(const int* __restrict__ rows,
                                  const int* __restrict__ cols,
                                  const float* __restrict__ vals,
                                  const float* __restrict__ user_emb,
                                  const float* __restrict__ item_emb,
                                  float* __restrict__ dst,
                                  int n_edges, int U_) {
    long long t = (long long)blockIdx.x * TPB + threadIdx.x;
    int e = (int)(t >> 4);
    if (e >= n_edges) return;
    int lane = (int)(t & 15);

    int r = rows[e];
    int c = cols[e];
    float v = vals[e];

    const float* srow = (c < U_) ? (user_emb + (long long)c * D64)
                                 : (item_emb + (long long)(c - U_) * D64);
    const float4* s = reinterpret_cast<const float4*>(srow) + lane;
    float4 x = *s;
    x.x *= v; x.y *= v; x.z *= v; x.w *= v;

    float4* d = reinterpret_cast<float4*>(dst + (long long)r * D64) + lane;
    asm volatile("red.global.add.v4.f32 [%0], {%1,%2,%3,%4};"
                 :: "l"(d), "f"(x.x), "f"(x.y), "f"(x.z), "f"(x.w)
                 : "memory");
}

extern "C" void kernel_launch(void* const* d_in, const int* in_sizes, int n_in,
                              void* d_out, int out_size) {
    const float* user_emb  = (const float*)d_in[0];
    const float* item_emb  = (const float*)d_in[1];
    const int*   g_rows    = (const int*)  d_in[2];
    const int*   g_cols    = (const int*)  d_in[3];
    const float* g_vals    = (const float*)d_in[4];
    const int*   u_rows    = (const int*)  d_in[5];
    const int*   u_cols    = (const int*)  d_in[6];
    const float* u_vals    = (const float*)d_in[7];
    const int*   i_rows    = (const int*)  d_in[8];
    const int*   i_cols    = (const int*)  d_in[9];
    const float* i_vals    = (const float*)d_in[10];

    float* out = (float*)d_out;

    const int U_ = in_sizes[0] / D64;       // 100000
    const int I_ = in_sizes[1] / D64;       // 50000
    const int N_ = U_ + I_;                 // 150000
    const int EG = in_sizes[2];             // graph edges
    const int EU = in_sizes[5];             // user edges
    const int EI = in_sizes[8];             // item edges

    // Zero all accumulation targets (entire output).
    cudaMemsetAsync(d_out, 0, (size_t)out_size * sizeof(float), 0);

    float* dst_graph = out;                              // all_emb1 (user+item)
    float* dst_user2 = out + (long long)N_ * D64;        // user_emb2
    float* dst_item2 = out + (long long)(N_ + U_) * D64; // item_emb2

    {
        long long threads = (long long)EG * 16;
        int blocks = (int)((threads + TPB - 1) / TPB);
        spmm_edges_concat<<<blocks, TPB>>>(g_rows, g_cols, g_vals,
                                           user_emb, item_emb,
                                           dst_graph, EG, U_);
    }
    {
        long long threads = (long long)EU * 16;
        int blocks = (int)((threads + TPB - 1) / TPB);
        spmm_edges<<<blocks, TPB>>>(u_rows, u_cols, u_vals,
                                    user_emb, dst_user2, EU);
    }
    {
        long long threads = (long long)EI * 16;
        int blocks = (int)((threads + TPB - 1) / TPB);
        spmm_edges<<<blocks, TPB>>>(i_rows, i_cols, i_vals,
                                    item_emb, dst_item2, EI);
    }
}